// round 6
// baseline (speedup 1.0000x reference)
#include <cuda_runtime.h>
#include <cuda_bf16.h>

#define EMBED_DIM 128
#define MAX_ATOM_TYPE 119
#define ROW 132                                    // padded row: 528B, 16B aligned
#define W_ELEMS (EMBED_DIM * MAX_ATOM_TYPE)        // 15232
#define TABLE_ELEMS (MAX_ATOM_TYPE * ROW)
#define GRP 8                                      // atoms per group (balance granule)

// Fused table T[t][e] = W[e][t] + b[e]; 62.8KB, L1-resident in every SM during
// the gather kernel (no smem used; streaming stores don't allocate in L1).
__device__ float g_table[TABLE_ELEMS];

__global__ void build_table_kernel(const float* __restrict__ W,
                                   const float* __restrict__ b)
{
    int i = blockIdx.x * blockDim.x + threadIdx.x;
    if (i < W_ELEMS) {
        int e = i / MAX_ATOM_TYPE;
        int t = i - e * MAX_ATOM_TYPE;
        g_table[t * ROW + e] = W[i] + __ldg(&b[e]);
    }
}

// Warp-per-atom-range gather. Each warp owns a CONTIGUOUS balanced range of
// 8-atom groups (quot/rem partition: max imbalance = 1 group ~ 1%), fixing the
// 3-vs-4 chunk tail imbalance of the grid-stride version. Per atom: scalar
// broadcast LDG of the index (L1-hit), LDG.128 of the lane's 16B table slot
// (L1-resident), streaming STG.128 of the 512B output row.
__global__ void __launch_bounds__(256, 8)
embed_atom_kernel(const int* __restrict__ atom_type,
                  float4* __restrict__ out,        // [N, 32] float4 view
                  int n)
{
    const int warp = threadIdx.x >> 5;
    const int lane = threadIdx.x & 31;
    const int gwarp = blockIdx.x * (blockDim.x >> 5) + warp;
    const int nwarps = gridDim.x * (blockDim.x >> 5);

    const int ngroups = n >> 3;                      // full 8-atom groups
    const int q = ngroups / nwarps;
    const int r = ngroups - q * nwarps;
    const int begin = gwarp * q + (gwarp < r ? gwarp : r);
    const int end   = begin + q + (gwarp < r ? 1 : 0);

    const float* lane_tab = g_table + (lane << 2);   // lane's 16B slot in a row

    for (int g = begin; g < end; g++) {
        const int base = g << 3;
        const int* idx = atom_type + base;
        float4* orow = out + (size_t)base * 32 + lane;

        #pragma unroll
        for (int k = 0; k < GRP; k++) {
            int t = __ldg(&idx[k]);                  // scalar broadcast, L1-hit
            float4 v = *reinterpret_cast<const float4*>(lane_tab + t * ROW);
            __stcs(&orow[(size_t)k * 32], v);        // streaming STG.128
        }
    }

    // tail (n not multiple of 8): last warp group handles leftovers
    for (int a = (ngroups << 3) + gwarp; a < n; a += nwarps) {
        int t = __ldg(&atom_type[a]);
        float4 v = *reinterpret_cast<const float4*>(lane_tab + t * ROW);
        __stcs(&out[(size_t)a * 32 + lane], v);
    }
}

extern "C" void kernel_launch(void* const* d_in, const int* in_sizes, int n_in,
                              void* d_out, int out_size)
{
    const int*   atom_type = (const int*)d_in[0];
    const float* W         = (const float*)d_in[1];
    const float* b         = (const float*)d_in[2];
    float4*      out       = (float4*)d_out;
    int n = in_sizes[0];

    build_table_kernel<<<(W_ELEMS + 255) / 256, 256>>>(W, b);
    embed_atom_kernel<<<148 * 8, 256>>>(atom_type, out, n);
}